// round 9
// baseline (speedup 1.0000x reference)
#include <cuda_runtime.h>
#include <cstdint>

#define HH 128
#define WW 192
#define CC_TOT 256
#define BB 8
#define TILE_W 32
#define TILE_H 16
#define HALO_H 24
#define CHUNK 4
#define NCHUNK (CC_TOT / CHUNK)
#define NT 384
#define PLANE ((size_t)HH * WW)

#define HROW 176                      // 44 floats/row: conflict-free at X=8
#define CROW 144                      // 36 floats/row
#define PSEC (HALO_H * HROW)          // 4224
#define CSEC (TILE_H * CROW)          // 2304
#define PREV_BUF (CHUNK * PSEC)       // 16896
#define CURR_BUF (CHUNK * CSEC)       // 9216
#define SM_PREV 0
#define SM_CURR (3 * PREV_BUF)        // 50688
#define SM_SSP  (SM_CURR + 3 * CURR_BUF)  // 78336
#define SM_CIV  (SM_SSP + PSEC)           // 82560 (curr inv-norms, 16 rows x 144B)
#define SMEM_BYTES (SM_CIV + TILE_H * CROW)  // 84864 -> 2 CTAs/SM

typedef unsigned long long u64;

__device__ __forceinline__ void F2(u64 &d, u64 a, u64 b) {
    asm("fma.rn.f32x2 %0, %1, %2, %0;" : "+l"(d) : "l"(a), "l"(b));
}
__device__ __forceinline__ u64 M2(u64 a, u64 b) {
    u64 d; asm("mul.rn.f32x2 %0, %1, %2;" : "=l"(d) : "l"(a), "l"(b)); return d;
}
__device__ __forceinline__ u64 PK(unsigned a, unsigned b) {
    u64 d; asm("mov.b64 %0, {%1, %2};" : "=l"(d) : "r"(a), "r"(b)); return d;
}
__device__ __forceinline__ unsigned LOW(u64 a) {
    unsigned l, h; asm("mov.b64 {%0, %1}, %2;" : "=r"(l), "=r"(h) : "l"(a)); return l;
}
__device__ __forceinline__ unsigned HIW(u64 a) {
    unsigned l, h; asm("mov.b64 {%0, %1}, %2;" : "=r"(l), "=r"(h) : "l"(a)); return h;
}
__device__ __forceinline__ float FL(u64 a) { return __uint_as_float(LOW(a)); }
__device__ __forceinline__ float FH(u64 a) { return __uint_as_float(HIW(a)); }
__device__ __forceinline__ void cp16(uint32_t dst, const void* src, int szbytes) {
    asm volatile("cp.async.cg.shared.global [%0], [%1], 16, %2;\n"
                 :: "r"(dst), "l"(src), "r"(szbytes) : "memory");
}
__device__ __forceinline__ ulonglong2 LD2(const void* p) {
    return *reinterpret_cast<const ulonglong2*>(p);
}
__device__ __forceinline__ u64 LD1(const void* p) {
    return *reinterpret_cast<const u64*>(p);
}
__device__ __forceinline__ float GRD(float v) { return v > 0.f ? rsqrtf(v) : 0.f; }

__global__ void __launch_bounds__(NT, 2)
corr_kernel(const float* __restrict__ curr, const float* __restrict__ prev,
            float* __restrict__ out)
{
    extern __shared__ char smem[];

    const int tid = threadIdx.x;
    const int grp = tid >> 6;          // 6 groups of 64 threads
    const int gt  = tid & 63;
    const int xg  = gt & 3;            // 4 x-groups of 8 pixels
    const int ty  = gt >> 2;           // 16 rows
    const int x0  = blockIdx.x * TILE_W;
    const int y0  = blockIdx.y * TILE_H;
    const int bb  = blockIdx.z;

    const char* currB = (const char*)(curr + (size_t)bb * CC_TOT * PLANE);
    const char* prevB = (const char*)(prev + (size_t)bb * CC_TOT * PLANE);
    const uint32_t smA = (uint32_t)__cvta_generic_to_shared(smem);

    // ---- staging precompute ----
    const int psy = tid / 10, psx = tid - psy * 10;     // 240 prev f4 slots
    const int pgy = y0 - 4 + psy, pgx = x0 - 4 + psx * 4;
    const bool doP = (tid < 240);
    const bool pok = doP && ((unsigned)pgy < HH) && ((unsigned)pgx < WW);
    const int pOff = pok ? (pgy * WW + pgx) * 4 : 0;
    const int psz  = pok ? 16 : 0;
    const uint32_t pRel = (uint32_t)(psy * HROW + psx * 16);
    const bool doC = (tid >= 256);                      // 128 curr f4 slots
    const int cslot = tid - 256;
    const int csy = cslot >> 3, csx = cslot & 7;
    const int cOff = ((y0 + csy) * WW + x0 + csx * 4) * 4;
    const uint32_t cRel = (uint32_t)(csy * CROW + csx * 16);

    // ---- boundary prev-sq: 112 slots on G3(56)/G4(56) ----
    int fbj = -1;
    if (grp == 3)      { if (gt < 56) fbj = gt; }
    else if (grp == 4) { if (gt < 56) fbj = 56 + gt; }
    const bool doFB = (fbj >= 0);
    int fbRow = 0, fbCol = 0;
    if (fbj >= 0) {
        if (fbj < 40)      { fbRow = fbj / 10; fbCol = fbj - fbRow * 10; }
        else if (fbj < 80) { int i = fbj - 40; fbRow = 20 + i / 10; fbCol = i - (i / 10) * 10; }
        else               { int i = fbj - 80; fbRow = 4 + (i >> 1); fbCol = (i & 1) ? 9 : 0; }
    }
    const uint32_t fbOff = (uint32_t)(fbRow * HROW + fbCol * 16);

    // ---- accumulators ----
    // G0: acc[0..19]=o0..4 (dy-4), acc[20..23]=o13 (dy0 dx-4)
    // G1: acc[0..19]=o5..9 (dy-2), acc[20..23]=o19 (dy0 dx+4)
    // G2: acc[0..19]=o14..18 (dy0 dx-2..2) + interior sq + curr ssq
    // G3: acc[0..19]=o23..27 (dy+2) + FB
    // G4: acc[0..19]=o28..32 (dy+4) + FB
    // G5: acc[0..11]=o10..12 (dy-1), acc[12..23]=o20..22 (dy+1)
    u64 acc[24];
    #pragma unroll
    for (int i = 0; i < 24; i++) acc[i] = 0ull;
    u64 ssq01 = 0ull, ssq23 = 0ull, ssq45 = 0ull, ssq67 = 0ull;  // G2 only
    u64 sq0 = 0ull, sq1 = 0ull, sq2 = 0ull, sq3 = 0ull;          // G2 only
    u64 fbA = 0ull, fbB = 0ull;                                  // G3/G4

    auto issue = [&](const char* srcP, const char* srcC, uint32_t dP, uint32_t dC) {
        #pragma unroll
        for (int cc = 0; cc < CHUNK; cc++) {
            const size_t so = (size_t)cc * PLANE * 4;
            if (doP) cp16(dP + cc * PSEC + pRel, srcP + so + pOff, psz);
            if (doC) cp16(dC + cc * CSEC + cRel, srcC + so + cOff, 16);
        }
        asm volatile("cp.async.commit_group;\n" ::: "memory");
    };

    issue(prevB, currB, smA + SM_PREV, smA + SM_CURR);
    issue(prevB + (size_t)CHUNK * PLANE * 4, currB + (size_t)CHUNK * PLANE * 4,
          smA + SM_PREV + PREV_BUF, smA + SM_CURR + CURR_BUF);

    const char* srcPs = prevB + (size_t)2 * CHUNK * PLANE * 4;
    const char* srcCs = currB + (size_t)2 * CHUNK * PLANE * 4;
    int bC = 0, bS = 2;

    const int tyOff = ty * HROW + xg * 32;
    const int cvOff = ty * CROW + xg * 32;

#define FROW(O, RB) do { \
    const ulonglong2 q0 = LD2(RB), q1 = LD2((RB) + 16), q2 = LD2((RB) + 32), q3 = LD2((RB) + 48); \
    F2(acc[(O)*4+0],cv01,q0.x); F2(acc[(O)*4+1],cv23,q0.y); F2(acc[(O)*4+2],cv45,q1.x); F2(acc[(O)*4+3],cv67,q1.y); \
    F2(acc[(O)*4+4],cv01,q0.y); F2(acc[(O)*4+5],cv23,q1.x); F2(acc[(O)*4+6],cv45,q1.y); F2(acc[(O)*4+7],cv67,q2.x); \
    F2(acc[(O)*4+8],cv01,q1.x); F2(acc[(O)*4+9],cv23,q1.y); F2(acc[(O)*4+10],cv45,q2.x); F2(acc[(O)*4+11],cv67,q2.y); \
    F2(acc[(O)*4+12],cv01,q1.y); F2(acc[(O)*4+13],cv23,q2.x); F2(acc[(O)*4+14],cv45,q2.y); F2(acc[(O)*4+15],cv67,q3.x); \
    F2(acc[(O)*4+16],cv01,q2.x); F2(acc[(O)*4+17],cv23,q2.y); F2(acc[(O)*4+18],cv45,q3.x); F2(acc[(O)*4+19],cv67,q3.y); \
} while (0)

#define MROW(O, RB) do { \
    const unsigned f3 = *(const unsigned*)((RB) + 12); \
    const ulonglong2 q1 = LD2((RB) + 16), q2 = LD2((RB) + 32); \
    const unsigned f12 = *(const unsigned*)((RB) + 48); \
    const u64 P34 = PK(f3, LOW(q1.x)),      P56 = PK(HIW(q1.x), LOW(q1.y)); \
    const u64 P78 = PK(HIW(q1.y), LOW(q2.x)), P9A = PK(HIW(q2.x), LOW(q2.y)); \
    const u64 PBC = PK(HIW(q2.y), f12); \
    F2(acc[(O)*4+0],cv01,P34);  F2(acc[(O)*4+1],cv23,P56);  F2(acc[(O)*4+2],cv45,P78);  F2(acc[(O)*4+3],cv67,P9A); \
    F2(acc[(O)*4+4],cv01,q1.x); F2(acc[(O)*4+5],cv23,q1.y); F2(acc[(O)*4+6],cv45,q2.x); F2(acc[(O)*4+7],cv67,q2.y); \
    F2(acc[(O)*4+8],cv01,P56);  F2(acc[(O)*4+9],cv23,P78);  F2(acc[(O)*4+10],cv45,P9A); F2(acc[(O)*4+11],cv67,PBC); \
} while (0)

#define PREAMBLE \
    const char* secB = pbuf + cc * PSEC; \
    const char* rowB = secB + tyOff; \
    const char* cvP  = cbuf + cc * CSEC + cvOff; \
    const ulonglong2 CA = LD2(cvP), CB = LD2(cvP + 16); \
    const u64 cv01 = CA.x, cv23 = CA.y, cv45 = CB.x, cv67 = CB.y;

    #pragma unroll 1
    for (int k = 0; k < NCHUNK; k++) {
        if (k < NCHUNK - 1) asm volatile("cp.async.wait_group 1;\n" ::: "memory");
        else                asm volatile("cp.async.wait_group 0;\n" ::: "memory");
        __syncthreads();

        if (k < NCHUNK - 2) {
            issue(srcPs, srcCs, smA + SM_PREV + bS * PREV_BUF, smA + SM_CURR + bS * CURR_BUF);
            srcPs += (size_t)CHUNK * PLANE * 4;
            srcCs += (size_t)CHUNK * PLANE * 4;
            bS = (bS == 2) ? 0 : bS + 1;
        }

        const char* pbuf = smem + SM_PREV + bC * PREV_BUF;
        const char* cbuf = smem + SM_CURR + bC * CURR_BUF;

        if (grp == 0) {
            #pragma unroll
            for (int cc = 0; cc < CHUNK; cc++) {
                PREAMBLE
                FROW(0, rowB);                      // dy=-4: o0..4
                const ulonglong2 z0 = LD2(rowB + 704), z1 = LD2(rowB + 720);  // dy0 dx-4
                F2(acc[20],cv01,z0.x); F2(acc[21],cv23,z0.y);
                F2(acc[22],cv45,z1.x); F2(acc[23],cv67,z1.y);
            }
        } else if (grp == 1) {
            #pragma unroll
            for (int cc = 0; cc < CHUNK; cc++) {
                PREAMBLE
                FROW(0, rowB + 352);                // dy=-2: o5..9
                const ulonglong2 z2 = LD2(rowB + 736), z3 = LD2(rowB + 752);  // dy0 dx+4
                F2(acc[20],cv01,z2.x); F2(acc[21],cv23,z2.y);
                F2(acc[22],cv45,z3.x); F2(acc[23],cv67,z3.y);
            }
        } else if (grp == 2) {
            #pragma unroll
            for (int cc = 0; cc < CHUNK; cc++) {
                PREAMBLE
                F2(ssq01, cv01, cv01); F2(ssq23, cv23, cv23);
                F2(ssq45, cv45, cv45); F2(ssq67, cv67, cv67);
                // dy0 dx{-2..2}: floats 2..13 of dy0 row
                const u64 d23 = LD1(rowB + 712);
                const ulonglong2 q1 = LD2(rowB + 720), q2 = LD2(rowB + 736);
                const u64 d1213 = LD1(rowB + 752);
                F2(sq0, q1.x, q1.x); F2(sq1, q1.y, q1.y);
                F2(sq2, q2.x, q2.x); F2(sq3, q2.y, q2.y);
                const u64 P34 = PK(HIW(d23), LOW(q1.x)), P56 = PK(HIW(q1.x), LOW(q1.y));
                const u64 P78 = PK(HIW(q1.y), LOW(q2.x)), P9A = PK(HIW(q2.x), LOW(q2.y));
                const u64 PBC = PK(HIW(q2.y), LOW(d1213));
                F2(acc[0],cv01,d23);   F2(acc[1],cv23,q1.x);  F2(acc[2],cv45,q1.y);  F2(acc[3],cv67,q2.x);   // dx-2
                F2(acc[4],cv01,P34);   F2(acc[5],cv23,P56);   F2(acc[6],cv45,P78);   F2(acc[7],cv67,P9A);    // dx-1
                F2(acc[8],cv01,q1.x);  F2(acc[9],cv23,q1.y);  F2(acc[10],cv45,q2.x); F2(acc[11],cv67,q2.y);  // dx0
                F2(acc[12],cv01,P56);  F2(acc[13],cv23,P78);  F2(acc[14],cv45,P9A);  F2(acc[15],cv67,PBC);   // dx+1
                F2(acc[16],cv01,q1.y); F2(acc[17],cv23,q2.x); F2(acc[18],cv45,q2.y); F2(acc[19],cv67,d1213); // dx+2
            }
        } else if (grp == 3) {
            #pragma unroll
            for (int cc = 0; cc < CHUNK; cc++) {
                PREAMBLE
                if (doFB) { const ulonglong2 v = LD2(secB + fbOff); F2(fbA, v.x, v.x); F2(fbB, v.y, v.y); }
                FROW(0, rowB + 1056);               // dy=+2: o23..27
            }
        } else if (grp == 4) {
            #pragma unroll
            for (int cc = 0; cc < CHUNK; cc++) {
                PREAMBLE
                if (doFB) { const ulonglong2 v = LD2(secB + fbOff); F2(fbA, v.x, v.x); F2(fbB, v.y, v.y); }
                FROW(0, rowB + 1408);               // dy=+4: o28..32
            }
        } else {
            #pragma unroll
            for (int cc = 0; cc < CHUNK; cc++) {
                PREAMBLE
                MROW(0, rowB + 528);                // dy=-1: o10..12
                MROW(3, rowB + 880);                // dy=+1: o20..22
            }
        }
        bC = (bC == 2) ? 0 : bC + 1;
    }

    // ---- epilogue: norms to smem ----
    {
        char* sspB = smem + SM_SSP;
        if (grp == 2) {
            // interior prev inv-norms
            float4 w0, w1;
            w0.x = GRD(FL(sq0)); w0.y = GRD(FH(sq0)); w0.z = GRD(FL(sq1)); w0.w = GRD(FH(sq1));
            w1.x = GRD(FL(sq2)); w1.y = GRD(FH(sq2)); w1.z = GRD(FL(sq3)); w1.w = GRD(FH(sq3));
            char* dst = sspB + (ty + 4) * HROW + xg * 32 + 16;
            *(float4*)dst = w0;
            *(float4*)(dst + 16) = w1;
            // curr inv-norms
            float4 c0, c1;
            c0.x = rsqrtf(FL(ssq01)); c0.y = rsqrtf(FH(ssq01));
            c0.z = rsqrtf(FL(ssq23)); c0.w = rsqrtf(FH(ssq23));
            c1.x = rsqrtf(FL(ssq45)); c1.y = rsqrtf(FH(ssq45));
            c1.z = rsqrtf(FL(ssq67)); c1.w = rsqrtf(FH(ssq67));
            char* cdst = smem + SM_CIV + ty * CROW + xg * 32;
            *(float4*)cdst = c0;
            *(float4*)(cdst + 16) = c1;
        }
        if (doFB) {
            float4 w;
            w.x = GRD(FL(fbA)); w.y = GRD(FH(fbA)); w.z = GRD(FL(fbB)); w.w = GRD(FH(fbB));
            *(float4*)(sspB + fbOff) = w;
        }
    }
    __syncthreads();

    u64 inv01, inv23, inv45, inv67;
    {
        const char* civ = smem + SM_CIV + ty * CROW + xg * 32;
        const ulonglong2 IA = LD2(civ), IB = LD2(civ + 16);
        inv01 = IA.x; inv23 = IA.y; inv45 = IB.x; inv67 = IB.y;
    }

    const char* srow = smem + SM_SSP + tyOff;
    char* outBase = (char*)(out + ((size_t)bb * 33 * HH + (y0 + ty)) * WW + x0 + xg * 8);

#define OST(PL, O, B0, B1, B2, B3) do { \
    ulonglong2 r0, r1; \
    r0.x = M2(M2(acc[(O)*4+0], inv01), (B0)); \
    r0.y = M2(M2(acc[(O)*4+1], inv23), (B1)); \
    r1.x = M2(M2(acc[(O)*4+2], inv45), (B2)); \
    r1.y = M2(M2(acc[(O)*4+3], inv67), (B3)); \
    char* _op = outBase + (size_t)(PL) * (PLANE * 4); \
    *(ulonglong2*)_op = r0; \
    *(ulonglong2*)(_op + 16) = r1; \
} while (0)

#define EFROW(SR, PL, O) do { \
    const ulonglong2 q0 = LD2(srow + (SR)), q1 = LD2(srow + (SR) + 16); \
    const ulonglong2 q2 = LD2(srow + (SR) + 32), q3 = LD2(srow + (SR) + 48); \
    OST((PL)+0, (O)+0, q0.x, q0.y, q1.x, q1.y); \
    OST((PL)+1, (O)+1, q0.y, q1.x, q1.y, q2.x); \
    OST((PL)+2, (O)+2, q1.x, q1.y, q2.x, q2.y); \
    OST((PL)+3, (O)+3, q1.y, q2.x, q2.y, q3.x); \
    OST((PL)+4, (O)+4, q2.x, q2.y, q3.x, q3.y); \
} while (0)

#define EMROW(SR, PL, O) do { \
    const unsigned f3 = *(const unsigned*)(srow + (SR) + 12); \
    const ulonglong2 q1 = LD2(srow + (SR) + 16), q2 = LD2(srow + (SR) + 32); \
    const unsigned f12 = *(const unsigned*)(srow + (SR) + 48); \
    const u64 P34 = PK(f3, LOW(q1.x)),        P56 = PK(HIW(q1.x), LOW(q1.y)); \
    const u64 P78 = PK(HIW(q1.y), LOW(q2.x)), P9A = PK(HIW(q2.x), LOW(q2.y)); \
    const u64 PBC = PK(HIW(q2.y), f12); \
    OST((PL)+0, (O)+0, P34, P56, P78, P9A); \
    OST((PL)+1, (O)+1, q1.x, q1.y, q2.x, q2.y); \
    OST((PL)+2, (O)+2, P56, P78, P9A, PBC); \
} while (0)

    if (grp == 0) {
        EFROW(0, 0, 0);        // dy=-4: o0..4
        const ulonglong2 z0 = LD2(srow + 704), z1 = LD2(srow + 720);
        OST(13, 5, z0.x, z0.y, z1.x, z1.y);        // o13
    } else if (grp == 1) {
        EFROW(352, 5, 0);      // dy=-2: o5..9
        const ulonglong2 z2 = LD2(srow + 736), z3 = LD2(srow + 752);
        OST(19, 5, z2.x, z2.y, z3.x, z3.y);        // o19
    } else if (grp == 2) {
        const u64 d23 = LD1(srow + 712);
        const ulonglong2 q1 = LD2(srow + 720), q2 = LD2(srow + 736);
        const u64 d1213 = LD1(srow + 752);
        const u64 P34 = PK(HIW(d23), LOW(q1.x)), P56 = PK(HIW(q1.x), LOW(q1.y));
        const u64 P78 = PK(HIW(q1.y), LOW(q2.x)), P9A = PK(HIW(q2.x), LOW(q2.y));
        const u64 PBC = PK(HIW(q2.y), LOW(d1213));
        OST(14, 0, d23, q1.x, q1.y, q2.x);
        OST(15, 1, P34, P56, P78, P9A);
        OST(16, 2, q1.x, q1.y, q2.x, q2.y);
        OST(17, 3, P56, P78, P9A, PBC);
        OST(18, 4, q1.y, q2.x, q2.y, d1213);
    } else if (grp == 3) {
        EFROW(1056, 23, 0);    // dy=+2: o23..27
    } else if (grp == 4) {
        EFROW(1408, 28, 0);    // dy=+4: o28..32
    } else {
        EMROW(528, 10, 0);     // dy=-1: o10..12
        EMROW(880, 20, 3);     // dy=+1: o20..22
    }
}

extern "C" void kernel_launch(void* const* d_in, const int* in_sizes, int n_in,
                              void* d_out, int out_size)
{
    const float* curr = (const float*)d_in[0];
    const float* prev = (const float*)d_in[1];
    float* out = (float*)d_out;

    cudaFuncSetAttribute(corr_kernel, cudaFuncAttributeMaxDynamicSharedMemorySize, SMEM_BYTES);

    dim3 grid(WW / TILE_W, HH / TILE_H, BB);   // 384 blocks
    corr_kernel<<<grid, NT, SMEM_BYTES>>>(curr, prev, out);
}

// round 10
// speedup vs baseline: 1.7141x; 1.7141x over previous
#include <cuda_runtime.h>
#include <cstdint>

#define HH 128
#define WW 192
#define CC_TOT 256
#define BB 8
#define TILE_W 32
#define TILE_H 16
#define HALO_H 24
#define CHUNK 4
#define NCHUNK (CC_TOT / CHUNK)
#define NT 256
#define PLANE ((size_t)HH * WW)

#define HROW 176                      // 44 floats/row: conflict-free at X=8
#define CROW 144                      // 36 floats/row
#define PSEC (HALO_H * HROW)          // 4224
#define CSEC (TILE_H * CROW)          // 2304
#define PREV_BUF (CHUNK * PSEC)       // 16896
#define CURR_BUF (CHUNK * CSEC)       // 9216
#define SM_PREV 0
#define SM_CURR (3 * PREV_BUF)        // 50688
#define SM_SSP  (SM_CURR + 3 * CURR_BUF)  // 78336
#define SM_CIV  (SM_SSP + PSEC)           // 82560
#define SMEM_BYTES (SM_CIV + TILE_H * CROW)  // 84864 -> 2 CTAs/SM

typedef unsigned long long u64;

__device__ __forceinline__ void F2(u64 &d, u64 a, u64 b) {
    asm("fma.rn.f32x2 %0, %1, %2, %0;" : "+l"(d) : "l"(a), "l"(b));
}
__device__ __forceinline__ u64 M2(u64 a, u64 b) {
    u64 d; asm("mul.rn.f32x2 %0, %1, %2;" : "=l"(d) : "l"(a), "l"(b)); return d;
}
__device__ __forceinline__ u64 PK(unsigned a, unsigned b) {
    u64 d; asm("mov.b64 %0, {%1, %2};" : "=l"(d) : "r"(a), "r"(b)); return d;
}
__device__ __forceinline__ unsigned LOW(u64 a) {
    unsigned l, h; asm("mov.b64 {%0, %1}, %2;" : "=r"(l), "=r"(h) : "l"(a)); return l;
}
__device__ __forceinline__ unsigned HIW(u64 a) {
    unsigned l, h; asm("mov.b64 {%0, %1}, %2;" : "=r"(l), "=r"(h) : "l"(a)); return h;
}
__device__ __forceinline__ float FL(u64 a) { return __uint_as_float(LOW(a)); }
__device__ __forceinline__ float FH(u64 a) { return __uint_as_float(HIW(a)); }
__device__ __forceinline__ void cp16(uint32_t dst, const void* src, int szbytes) {
    asm volatile("cp.async.cg.shared.global [%0], [%1], 16, %2;\n"
                 :: "r"(dst), "l"(src), "r"(szbytes) : "memory");
}
__device__ __forceinline__ ulonglong2 LD2(const void* p) {
    return *reinterpret_cast<const ulonglong2*>(p);
}
__device__ __forceinline__ u64 LD1(const void* p) {
    return *reinterpret_cast<const u64*>(p);
}
__device__ __forceinline__ float GRD(float v) { return v > 0.f ? rsqrtf(v) : 0.f; }

__global__ void __launch_bounds__(NT, 2)
corr_kernel(const float* __restrict__ curr, const float* __restrict__ prev,
            float* __restrict__ out)
{
    extern __shared__ char smem[];

    const int tid = threadIdx.x;
    const int grp = tid >> 6;          // 4 groups of 64 threads
    const int gt  = tid & 63;
    const int xg  = gt & 3;            // 4 x-groups of 8 pixels
    const int ty  = gt >> 2;           // 16 rows
    const int x0  = blockIdx.x * TILE_W;
    const int y0  = blockIdx.y * TILE_H;
    const int bb  = blockIdx.z;

    const char* currB = (const char*)(curr + (size_t)bb * CC_TOT * PLANE);
    const char* prevB = (const char*)(prev + (size_t)bb * CC_TOT * PLANE);
    const uint32_t smA = (uint32_t)__cvta_generic_to_shared(smem);

    // ---- staging precompute ----
    const int psy = tid / 10, psx = tid - psy * 10;     // 240 prev f4 slots
    const int pgy = y0 - 4 + psy, pgx = x0 - 4 + psx * 4;
    const bool doP = (tid < 240);
    const bool pok = doP && ((unsigned)pgy < HH) && ((unsigned)pgx < WW);
    const int pOff = pok ? (pgy * WW + pgx) * 4 : 0;
    const int psz  = pok ? 16 : 0;
    const uint32_t pRel = (uint32_t)(psy * HROW + psx * 16);
    const bool doC = (tid >= 128);                      // 128 curr f4 slots
    const int cslot = tid - 128;
    const int csy = cslot >> 3, csx = cslot & 7;
    const int cOff = ((y0 + csy) * WW + x0 + csx * 4) * 4;
    const uint32_t cRel = (uint32_t)(csy * CROW + csx * 16);

    // ---- boundary prev-sq: 112 slots on G1(56)/G3(56) ----
    int fbj = -1;
    if (grp == 1)      { if (gt < 56) fbj = gt; }
    else if (grp == 3) { if (gt < 56) fbj = 56 + gt; }
    const bool doFB = (fbj >= 0);
    int fbRow = 0, fbCol = 0;
    if (fbj >= 0) {
        if (fbj < 40)      { fbRow = fbj / 10; fbCol = fbj - fbRow * 10; }
        else if (fbj < 80) { int i = fbj - 40; fbRow = 20 + i / 10; fbCol = i - (i / 10) * 10; }
        else               { int i = fbj - 80; fbRow = 4 + (i >> 1); fbCol = (i & 1) ? 9 : 0; }
    }
    const uint32_t fbOff = (uint32_t)(fbRow * HROW + fbCol * 16);

    // ---- accumulators ----
    // G0: acc[0..19]=o0..4 (dy-4), acc[20..31]=o10..12 (dy-1); owns ssq
    // G1: acc[0..19]=o5..9 (dy-2), acc[20..31]=o20..22 (dy+1); fb
    // G2: acc[0..27]=o13..19 (dy0), acc[28..35]=o23,o24 (dy+2 dx-4,-2); owns sq
    // G3: acc[0..19]=o28..32 (dy+4), acc[20..31]=o25..27 (dy+2 dx0,2,4); fb
    u64 acc[36];
    #pragma unroll
    for (int i = 0; i < 36; i++) acc[i] = 0ull;
    u64 ssq01 = 0ull, ssq23 = 0ull, ssq45 = 0ull, ssq67 = 0ull;  // G0 only
    u64 sq0 = 0ull, sq1 = 0ull, sq2 = 0ull, sq3 = 0ull;          // G2 only
    u64 fbA = 0ull, fbB = 0ull;                                  // G1/G3

    auto issue = [&](const char* srcP, const char* srcC, uint32_t dP, uint32_t dC) {
        #pragma unroll
        for (int cc = 0; cc < CHUNK; cc++) {
            const size_t so = (size_t)cc * PLANE * 4;
            if (doP) cp16(dP + cc * PSEC + pRel, srcP + so + pOff, psz);
            if (doC) cp16(dC + cc * CSEC + cRel, srcC + so + cOff, 16);
        }
        asm volatile("cp.async.commit_group;\n" ::: "memory");
    };

    issue(prevB, currB, smA + SM_PREV, smA + SM_CURR);
    issue(prevB + (size_t)CHUNK * PLANE * 4, currB + (size_t)CHUNK * PLANE * 4,
          smA + SM_PREV + PREV_BUF, smA + SM_CURR + CURR_BUF);

    const char* srcPs = prevB + (size_t)2 * CHUNK * PLANE * 4;
    const char* srcCs = currB + (size_t)2 * CHUNK * PLANE * 4;
    int bC = 0, bS = 2;

    const int tyOff = ty * HROW + xg * 32;
    const int cvOff = ty * CROW + xg * 32;

#define FROW(O, RB) do { \
    const ulonglong2 q0 = LD2(RB), q1 = LD2((RB) + 16), q2 = LD2((RB) + 32), q3 = LD2((RB) + 48); \
    F2(acc[(O)*4+0],cv01,q0.x); F2(acc[(O)*4+1],cv23,q0.y); F2(acc[(O)*4+2],cv45,q1.x); F2(acc[(O)*4+3],cv67,q1.y); \
    F2(acc[(O)*4+4],cv01,q0.y); F2(acc[(O)*4+5],cv23,q1.x); F2(acc[(O)*4+6],cv45,q1.y); F2(acc[(O)*4+7],cv67,q2.x); \
    F2(acc[(O)*4+8],cv01,q1.x); F2(acc[(O)*4+9],cv23,q1.y); F2(acc[(O)*4+10],cv45,q2.x); F2(acc[(O)*4+11],cv67,q2.y); \
    F2(acc[(O)*4+12],cv01,q1.y); F2(acc[(O)*4+13],cv23,q2.x); F2(acc[(O)*4+14],cv45,q2.y); F2(acc[(O)*4+15],cv67,q3.x); \
    F2(acc[(O)*4+16],cv01,q2.x); F2(acc[(O)*4+17],cv23,q2.y); F2(acc[(O)*4+18],cv45,q3.x); F2(acc[(O)*4+19],cv67,q3.y); \
} while (0)

#define MROW(O, RB) do { \
    const unsigned f3 = *(const unsigned*)((RB) + 12); \
    const ulonglong2 q1 = LD2((RB) + 16), q2 = LD2((RB) + 32); \
    const unsigned f12 = *(const unsigned*)((RB) + 48); \
    const u64 P34 = PK(f3, LOW(q1.x)),      P56 = PK(HIW(q1.x), LOW(q1.y)); \
    const u64 P78 = PK(HIW(q1.y), LOW(q2.x)), P9A = PK(HIW(q2.x), LOW(q2.y)); \
    const u64 PBC = PK(HIW(q2.y), f12); \
    F2(acc[(O)*4+0],cv01,P34);  F2(acc[(O)*4+1],cv23,P56);  F2(acc[(O)*4+2],cv45,P78);  F2(acc[(O)*4+3],cv67,P9A); \
    F2(acc[(O)*4+4],cv01,q1.x); F2(acc[(O)*4+5],cv23,q1.y); F2(acc[(O)*4+6],cv45,q2.x); F2(acc[(O)*4+7],cv67,q2.y); \
    F2(acc[(O)*4+8],cv01,P56);  F2(acc[(O)*4+9],cv23,P78);  F2(acc[(O)*4+10],cv45,P9A); F2(acc[(O)*4+11],cv67,PBC); \
} while (0)

#define PREAMBLE \
    const char* secB = pbuf + cc * PSEC; \
    const char* rowB = secB + tyOff; \
    const char* cvP  = cbuf + cc * CSEC + cvOff; \
    const ulonglong2 CA = LD2(cvP), CB = LD2(cvP + 16); \
    const u64 cv01 = CA.x, cv23 = CA.y, cv45 = CB.x, cv67 = CB.y;

    #pragma unroll 1
    for (int k = 0; k < NCHUNK; k++) {
        if (k < NCHUNK - 1) asm volatile("cp.async.wait_group 1;\n" ::: "memory");
        else                asm volatile("cp.async.wait_group 0;\n" ::: "memory");
        __syncthreads();

        if (k < NCHUNK - 2) {
            issue(srcPs, srcCs, smA + SM_PREV + bS * PREV_BUF, smA + SM_CURR + bS * CURR_BUF);
            srcPs += (size_t)CHUNK * PLANE * 4;
            srcCs += (size_t)CHUNK * PLANE * 4;
            bS = (bS == 2) ? 0 : bS + 1;
        }

        const char* pbuf = smem + SM_PREV + bC * PREV_BUF;
        const char* cbuf = smem + SM_CURR + bC * CURR_BUF;

        if (grp == 0) {
            #pragma unroll
            for (int cc = 0; cc < CHUNK; cc++) {
                PREAMBLE
                F2(ssq01, cv01, cv01); F2(ssq23, cv23, cv23);
                F2(ssq45, cv45, cv45); F2(ssq67, cv67, cv67);
                FROW(0, rowB);                      // dy=-4: o0..4
                MROW(5, rowB + 528);                // dy=-1: o10..12
            }
        } else if (grp == 1) {
            #pragma unroll
            for (int cc = 0; cc < CHUNK; cc++) {
                PREAMBLE
                if (doFB) { const ulonglong2 v = LD2(secB + fbOff); F2(fbA, v.x, v.x); F2(fbB, v.y, v.y); }
                FROW(0, rowB + 352);                // dy=-2: o5..9
                MROW(5, rowB + 880);                // dy=+1: o20..22
            }
        } else if (grp == 2) {
            #pragma unroll
            for (int cc = 0; cc < CHUNK; cc++) {
                PREAMBLE
                {   // dy=0: o13..19 + interior prev-sq
                    const char* rb = rowB + 704;
                    const ulonglong2 q0 = LD2(rb), q1 = LD2(rb + 16), q2 = LD2(rb + 32), q3 = LD2(rb + 48);
                    F2(sq0, q1.x, q1.x); F2(sq1, q1.y, q1.y); F2(sq2, q2.x, q2.x); F2(sq3, q2.y, q2.y);
                    const u64 P34 = PK(HIW(q0.y), LOW(q1.x)), P56 = PK(HIW(q1.x), LOW(q1.y));
                    const u64 P78 = PK(HIW(q1.y), LOW(q2.x)), P9A = PK(HIW(q2.x), LOW(q2.y));
                    const u64 PBC = PK(HIW(q2.y), LOW(q3.x));
                    F2(acc[0],cv01,q0.x);  F2(acc[1],cv23,q0.y);  F2(acc[2],cv45,q1.x);  F2(acc[3],cv67,q1.y);
                    F2(acc[4],cv01,q0.y);  F2(acc[5],cv23,q1.x);  F2(acc[6],cv45,q1.y);  F2(acc[7],cv67,q2.x);
                    F2(acc[8],cv01,P34);   F2(acc[9],cv23,P56);   F2(acc[10],cv45,P78);  F2(acc[11],cv67,P9A);
                    F2(acc[12],cv01,q1.x); F2(acc[13],cv23,q1.y); F2(acc[14],cv45,q2.x); F2(acc[15],cv67,q2.y);
                    F2(acc[16],cv01,P56);  F2(acc[17],cv23,P78);  F2(acc[18],cv45,P9A);  F2(acc[19],cv67,PBC);
                    F2(acc[20],cv01,q1.y); F2(acc[21],cv23,q2.x); F2(acc[22],cv45,q2.y); F2(acc[23],cv67,q3.x);
                    F2(acc[24],cv01,q2.x); F2(acc[25],cv23,q2.y); F2(acc[26],cv45,q3.x); F2(acc[27],cv67,q3.y);
                }
                {   // dy=+2 dx{-4,-2}: o23,o24
                    const char* rb = rowB + 1056;
                    const ulonglong2 q0 = LD2(rb), q1 = LD2(rb + 16);
                    const u64 q2lo = LD1(rb + 32);
                    F2(acc[28],cv01,q0.x); F2(acc[29],cv23,q0.y); F2(acc[30],cv45,q1.x); F2(acc[31],cv67,q1.y);
                    F2(acc[32],cv01,q0.y); F2(acc[33],cv23,q1.x); F2(acc[34],cv45,q1.y); F2(acc[35],cv67,q2lo);
                }
            }
        } else {
            #pragma unroll
            for (int cc = 0; cc < CHUNK; cc++) {
                PREAMBLE
                if (doFB) { const ulonglong2 v = LD2(secB + fbOff); F2(fbA, v.x, v.x); F2(fbB, v.y, v.y); }
                FROW(0, rowB + 1408);               // dy=+4: o28..32
                {   // dy=+2 dx{0,2,4}: o25,o26,o27
                    const char* rb = rowB + 1056;
                    const ulonglong2 q1 = LD2(rb + 16), q2 = LD2(rb + 32), q3 = LD2(rb + 48);
                    F2(acc[20],cv01,q1.x); F2(acc[21],cv23,q1.y); F2(acc[22],cv45,q2.x); F2(acc[23],cv67,q2.y);
                    F2(acc[24],cv01,q1.y); F2(acc[25],cv23,q2.x); F2(acc[26],cv45,q2.y); F2(acc[27],cv67,q3.x);
                    F2(acc[28],cv01,q2.x); F2(acc[29],cv23,q2.y); F2(acc[30],cv45,q3.x); F2(acc[31],cv67,q3.y);
                }
            }
        }
        bC = (bC == 2) ? 0 : bC + 1;
    }

    // ---- epilogue: norms into smem ----
    {
        char* sspB = smem + SM_SSP;
        if (grp == 0) {   // curr inv-norms to CIV
            float4 c0, c1;
            c0.x = rsqrtf(FL(ssq01)); c0.y = rsqrtf(FH(ssq01));
            c0.z = rsqrtf(FL(ssq23)); c0.w = rsqrtf(FH(ssq23));
            c1.x = rsqrtf(FL(ssq45)); c1.y = rsqrtf(FH(ssq45));
            c1.z = rsqrtf(FL(ssq67)); c1.w = rsqrtf(FH(ssq67));
            char* cdst = smem + SM_CIV + ty * CROW + xg * 32;
            *(float4*)cdst = c0;
            *(float4*)(cdst + 16) = c1;
        } else if (grp == 2) {   // interior prev inv-norms
            float4 w0, w1;
            w0.x = GRD(FL(sq0)); w0.y = GRD(FH(sq0)); w0.z = GRD(FL(sq1)); w0.w = GRD(FH(sq1));
            w1.x = GRD(FL(sq2)); w1.y = GRD(FH(sq2)); w1.z = GRD(FL(sq3)); w1.w = GRD(FH(sq3));
            char* dst = sspB + (ty + 4) * HROW + xg * 32 + 16;
            *(float4*)dst = w0;
            *(float4*)(dst + 16) = w1;
        }
        if (doFB) {
            float4 w;
            w.x = GRD(FL(fbA)); w.y = GRD(FH(fbA)); w.z = GRD(FL(fbB)); w.w = GRD(FH(fbB));
            *(float4*)(sspB + fbOff) = w;
        }
    }
    __syncthreads();

    u64 inv01, inv23, inv45, inv67;
    {
        const char* civ = smem + SM_CIV + ty * CROW + xg * 32;
        const ulonglong2 IA = LD2(civ), IB = LD2(civ + 16);
        inv01 = IA.x; inv23 = IA.y; inv45 = IB.x; inv67 = IB.y;
    }

    const char* srow = smem + SM_SSP + tyOff;
    char* outBase = (char*)(out + ((size_t)bb * 33 * HH + (y0 + ty)) * WW + x0 + xg * 8);

#define OST(PL, O, B0, B1, B2, B3) do { \
    ulonglong2 r0, r1; \
    r0.x = M2(M2(acc[(O)*4+0], inv01), (B0)); \
    r0.y = M2(M2(acc[(O)*4+1], inv23), (B1)); \
    r1.x = M2(M2(acc[(O)*4+2], inv45), (B2)); \
    r1.y = M2(M2(acc[(O)*4+3], inv67), (B3)); \
    char* _op = outBase + (size_t)(PL) * (PLANE * 4); \
    *(ulonglong2*)_op = r0; \
    *(ulonglong2*)(_op + 16) = r1; \
} while (0)

#define EFROW(SR, PL, O) do { \
    const ulonglong2 q0 = LD2(srow + (SR)), q1 = LD2(srow + (SR) + 16); \
    const ulonglong2 q2 = LD2(srow + (SR) + 32), q3 = LD2(srow + (SR) + 48); \
    OST((PL)+0, (O)+0, q0.x, q0.y, q1.x, q1.y); \
    OST((PL)+1, (O)+1, q0.y, q1.x, q1.y, q2.x); \
    OST((PL)+2, (O)+2, q1.x, q1.y, q2.x, q2.y); \
    OST((PL)+3, (O)+3, q1.y, q2.x, q2.y, q3.x); \
    OST((PL)+4, (O)+4, q2.x, q2.y, q3.x, q3.y); \
} while (0)

#define EMROW(SR, PL, O) do { \
    const unsigned f3 = *(const unsigned*)(srow + (SR) + 12); \
    const ulonglong2 q1 = LD2(srow + (SR) + 16), q2 = LD2(srow + (SR) + 32); \
    const unsigned f12 = *(const unsigned*)(srow + (SR) + 48); \
    const u64 P34 = PK(f3, LOW(q1.x)),        P56 = PK(HIW(q1.x), LOW(q1.y)); \
    const u64 P78 = PK(HIW(q1.y), LOW(q2.x)), P9A = PK(HIW(q2.x), LOW(q2.y)); \
    const u64 PBC = PK(HIW(q2.y), f12); \
    OST((PL)+0, (O)+0, P34, P56, P78, P9A); \
    OST((PL)+1, (O)+1, q1.x, q1.y, q2.x, q2.y); \
    OST((PL)+2, (O)+2, P56, P78, P9A, PBC); \
} while (0)

    if (grp == 0) {
        EFROW(0, 0, 0);        // dy=-4: o0..4
        EMROW(528, 10, 5);     // dy=-1: o10..12
    } else if (grp == 1) {
        EFROW(352, 5, 0);      // dy=-2: o5..9
        EMROW(880, 20, 5);     // dy=+1: o20..22
    } else if (grp == 2) {
        {   // dy=0: o13..19
            const ulonglong2 q0 = LD2(srow + 704), q1 = LD2(srow + 720);
            const ulonglong2 q2 = LD2(srow + 736), q3 = LD2(srow + 752);
            const u64 P34 = PK(HIW(q0.y), LOW(q1.x)), P56 = PK(HIW(q1.x), LOW(q1.y));
            const u64 P78 = PK(HIW(q1.y), LOW(q2.x)), P9A = PK(HIW(q2.x), LOW(q2.y));
            const u64 PBC = PK(HIW(q2.y), LOW(q3.x));
            OST(13, 0, q0.x, q0.y, q1.x, q1.y);
            OST(14, 1, q0.y, q1.x, q1.y, q2.x);
            OST(15, 2, P34, P56, P78, P9A);
            OST(16, 3, q1.x, q1.y, q2.x, q2.y);
            OST(17, 4, P56, P78, P9A, PBC);
            OST(18, 5, q1.y, q2.x, q2.y, q3.x);
            OST(19, 6, q2.x, q2.y, q3.x, q3.y);
        }
        {   // dy=+2 dx{-4,-2}: o23,o24
            const ulonglong2 q0 = LD2(srow + 1056), q1 = LD2(srow + 1072);
            const u64 q2lo = LD1(srow + 1088);
            OST(23, 7, q0.x, q0.y, q1.x, q1.y);
            OST(24, 8, q0.y, q1.x, q1.y, q2lo);
        }
    } else {
        EFROW(1408, 28, 0);    // dy=+4: o28..32
        {   // dy=+2 dx{0,2,4}: o25,o26,o27
            const ulonglong2 q1 = LD2(srow + 1072), q2 = LD2(srow + 1088), q3 = LD2(srow + 1104);
            OST(25, 5, q1.x, q1.y, q2.x, q2.y);
            OST(26, 6, q1.y, q2.x, q2.y, q3.x);
            OST(27, 7, q2.x, q2.y, q3.x, q3.y);
        }
    }
}

extern "C" void kernel_launch(void* const* d_in, const int* in_sizes, int n_in,
                              void* d_out, int out_size)
{
    const float* curr = (const float*)d_in[0];
    const float* prev = (const float*)d_in[1];
    float* out = (float*)d_out;

    cudaFuncSetAttribute(corr_kernel, cudaFuncAttributeMaxDynamicSharedMemorySize, SMEM_BYTES);

    dim3 grid(WW / TILE_W, HH / TILE_H, BB);   // 384 blocks
    corr_kernel<<<grid, NT, SMEM_BYTES>>>(curr, prev, out);
}

// round 12
// speedup vs baseline: 1.7787x; 1.0377x over previous
#include <cuda_runtime.h>
#include <cstdint>

#define HH 128
#define WW 192
#define CC_TOT 256
#define BB 8
#define TILE_W 32
#define TILE_H 16
#define HALO_H 24
#define CHUNK 4
#define NCHUNK (CC_TOT / CHUNK)
#define NT 256
#define PLANE ((size_t)HH * WW)

#define HROW 176
#define CROW 144
#define PSEC (HALO_H * HROW)              // 4224
#define CSEC (TILE_H * CROW)              // 2304
#define PREV_BUF (CHUNK * PSEC)           // 16896
#define CURR_BUF (CHUNK * CSEC)           // 9216
#define SM_PREV 0
#define SM_CURR (3 * PREV_BUF)            // 50688
#define SM_SSP  (SM_CURR + 3 * CURR_BUF)  // 78336
#define SM_CIV  (SM_SSP + PSEC)           // 82560
#define SMEM_BYTES (SM_CIV + TILE_H * CROW)  // 84864 -> 2 CTAs/SM

typedef unsigned long long u64;

__device__ __forceinline__ void F2(u64 &d, u64 a, u64 b) {
    asm("fma.rn.f32x2 %0, %1, %2, %0;" : "+l"(d) : "l"(a), "l"(b));
}
__device__ __forceinline__ u64 M2(u64 a, u64 b) {
    u64 d; asm("mul.rn.f32x2 %0, %1, %2;" : "=l"(d) : "l"(a), "l"(b)); return d;
}
__device__ __forceinline__ u64 PK(unsigned a, unsigned b) {
    u64 d; asm("mov.b64 %0, {%1, %2};" : "=l"(d) : "r"(a), "r"(b)); return d;
}
__device__ __forceinline__ unsigned LOW(u64 a) {
    unsigned l, h; asm("mov.b64 {%0, %1}, %2;" : "=r"(l), "=r"(h) : "l"(a)); return l;
}
__device__ __forceinline__ unsigned HIW(u64 a) {
    unsigned l, h; asm("mov.b64 {%0, %1}, %2;" : "=r"(l), "=r"(h) : "l"(a)); return h;
}
__device__ __forceinline__ float FL(u64 a) { return __uint_as_float(LOW(a)); }
__device__ __forceinline__ float FH(u64 a) { return __uint_as_float(HIW(a)); }
__device__ __forceinline__ void cp16(uint32_t dst, const void* src, int szbytes) {
    asm volatile("cp.async.cg.shared.global [%0], [%1], 16, %2;\n"
                 :: "r"(dst), "l"(src), "r"(szbytes) : "memory");
}
__device__ __forceinline__ ulonglong2 LD2(const void* p) {
    return *reinterpret_cast<const ulonglong2*>(p);
}
__device__ __forceinline__ u64 LD1(const void* p) {
    return *reinterpret_cast<const u64*>(p);
}
__device__ __forceinline__ float GRD(float v) { return v > 0.f ? rsqrtf(v) : 0.f; }

__global__ void __launch_bounds__(NT, 2)
corr_kernel(const float* __restrict__ curr, const float* __restrict__ prev,
            float* __restrict__ out)
{
    extern __shared__ char smem[];

    const int tid = threadIdx.x;
    const int grp = tid >> 6;          // 4 groups of 64 threads
    const int gt  = tid & 63;
    const int xg  = gt & 3;            // 4 x-groups of 8 pixels
    const int ty  = gt >> 2;           // 16 rows
    const int x0  = blockIdx.x * TILE_W;
    const int y0  = blockIdx.y * TILE_H;
    const int bb  = blockIdx.z;

    const char* currB = (const char*)(curr + (size_t)bb * CC_TOT * PLANE);
    const char* prevB = (const char*)(prev + (size_t)bb * CC_TOT * PLANE);
    const uint32_t smA = (uint32_t)__cvta_generic_to_shared(smem);

    // ---- staging precompute ----
    const int psy = tid / 10, psx = tid - psy * 10;   // 240 prev f4 slots (24 rows x 10)
    const int pgy = y0 - 4 + psy, pgx = x0 - 4 + psx * 4;
    const bool doP = (tid < 240);
    const bool pok = doP && ((unsigned)pgy < HH) && ((unsigned)pgx < WW);
    const int pOff = pok ? (pgy * WW + pgx) * 4 : 0;
    const int psz  = pok ? 16 : 0;
    const uint32_t pRel = (uint32_t)(psy * HROW + psx * 16);
    const bool doC = (tid >= 128);
    const int cslot = tid - 128;
    const int csy = cslot >> 3, csx = cslot & 7;
    const int cOff = ((y0 + csy) * WW + x0 + csx * 4) * 4;
    const uint32_t cRel = (uint32_t)(csy * CROW + csx * 16);

    // ---- boundary prev-sq: 112 slots on G1(56)/G3(56) ----
    int fbj = -1;
    if (grp == 1)      { if (gt < 56) fbj = gt; }
    else if (grp == 3) { if (gt < 56) fbj = 56 + gt; }
    const bool doFB = (fbj >= 0);
    int fbRow = 0, fbCol = 0;
    if (fbj >= 0) {
        if (fbj < 40)      { fbRow = fbj / 10; fbCol = fbj - fbRow * 10; }
        else if (fbj < 80) { int i = fbj - 40; fbRow = 20 + i / 10; fbCol = i - (i / 10) * 10; }
        else               { int i = fbj - 80; fbRow = 4 + (i >> 1); fbCol = (i & 1) ? 9 : 0; }
    }
    const uint32_t fbOff = (uint32_t)(fbRow * HROW + fbCol * 16);

    // ---- accumulators ----
    // G0: acc[0..19]=o0..4 (dy-4), acc[20..31]=o10..12 (dy-1), acc[32]=o23 pair01; aux=ssq
    // G1: acc[0..19]=o5..9 (dy-2), acc[20..31]=o20..22 (dy+1); aux[0..1]=fb
    // G2: acc[0..27]=o13..19 (dy0), acc[28..31]=o24, acc[32]=o23 pair23; aux=sq
    // G3: acc[0..19]=o28..32 (dy+4), acc[20..31]=o25..27, acc[32..33]=o23 pairs45/67; aux[0..1]=fb
    u64 acc[34];
    #pragma unroll
    for (int i = 0; i < 34; i++) acc[i] = 0ull;
    u64 aux[4];
    #pragma unroll
    for (int i = 0; i < 4; i++) aux[i] = 0ull;

    auto issue = [&](const char* srcP, const char* srcC, uint32_t dP, uint32_t dC) {
        #pragma unroll
        for (int cc = 0; cc < CHUNK; cc++) {
            const size_t so = (size_t)cc * PLANE * 4;
            if (doP) cp16(dP + cc * PSEC + pRel, srcP + so + pOff, psz);
            if (doC) cp16(dC + cc * CSEC + cRel, srcC + so + cOff, 16);
        }
        asm volatile("cp.async.commit_group;\n" ::: "memory");
    };

    issue(prevB, currB, smA + SM_PREV, smA + SM_CURR);
    issue(prevB + (size_t)CHUNK * PLANE * 4, currB + (size_t)CHUNK * PLANE * 4,
          smA + SM_PREV + PREV_BUF, smA + SM_CURR + CURR_BUF);

    const char* srcPs = prevB + (size_t)2 * CHUNK * PLANE * 4;
    const char* srcCs = currB + (size_t)2 * CHUNK * PLANE * 4;
    int bC = 0, bS = 2;

    const int tyOff = ty * HROW + xg * 32;
    const int cvOff = ty * CROW + xg * 32;

#define FROW(O, RB) do { \
    const ulonglong2 q0 = LD2(RB), q1 = LD2((RB) + 16), q2 = LD2((RB) + 32), q3 = LD2((RB) + 48); \
    F2(acc[(O)*4+0],cv01,q0.x); F2(acc[(O)*4+1],cv23,q0.y); F2(acc[(O)*4+2],cv45,q1.x); F2(acc[(O)*4+3],cv67,q1.y); \
    F2(acc[(O)*4+4],cv01,q0.y); F2(acc[(O)*4+5],cv23,q1.x); F2(acc[(O)*4+6],cv45,q1.y); F2(acc[(O)*4+7],cv67,q2.x); \
    F2(acc[(O)*4+8],cv01,q1.x); F2(acc[(O)*4+9],cv23,q1.y); F2(acc[(O)*4+10],cv45,q2.x); F2(acc[(O)*4+11],cv67,q2.y); \
    F2(acc[(O)*4+12],cv01,q1.y); F2(acc[(O)*4+13],cv23,q2.x); F2(acc[(O)*4+14],cv45,q2.y); F2(acc[(O)*4+15],cv67,q3.x); \
    F2(acc[(O)*4+16],cv01,q2.x); F2(acc[(O)*4+17],cv23,q2.y); F2(acc[(O)*4+18],cv45,q3.x); F2(acc[(O)*4+19],cv67,q3.y); \
} while (0)

#define MROW(O, RB) do { \
    const unsigned f3 = *(const unsigned*)((RB) + 12); \
    const ulonglong2 q1 = LD2((RB) + 16), q2 = LD2((RB) + 32); \
    const unsigned f12 = *(const unsigned*)((RB) + 48); \
    const u64 P34 = PK(f3, LOW(q1.x)),      P56 = PK(HIW(q1.x), LOW(q1.y)); \
    const u64 P78 = PK(HIW(q1.y), LOW(q2.x)), P9A = PK(HIW(q2.x), LOW(q2.y)); \
    const u64 PBC = PK(HIW(q2.y), f12); \
    F2(acc[(O)*4+0],cv01,P34);  F2(acc[(O)*4+1],cv23,P56);  F2(acc[(O)*4+2],cv45,P78);  F2(acc[(O)*4+3],cv67,P9A); \
    F2(acc[(O)*4+4],cv01,q1.x); F2(acc[(O)*4+5],cv23,q1.y); F2(acc[(O)*4+6],cv45,q2.x); F2(acc[(O)*4+7],cv67,q2.y); \
    F2(acc[(O)*4+8],cv01,P56);  F2(acc[(O)*4+9],cv23,P78);  F2(acc[(O)*4+10],cv45,P9A); F2(acc[(O)*4+11],cv67,PBC); \
} while (0)

#define PREAMBLE \
    const char* secB = pbuf + cc * PSEC; \
    const char* rowB = secB + tyOff; \
    const char* cvP  = cbuf + cc * CSEC + cvOff; \
    const ulonglong2 CA = LD2(cvP), CB = LD2(cvP + 16); \
    const u64 cv01 = CA.x, cv23 = CA.y, cv45 = CB.x, cv67 = CB.y;

    #pragma unroll 1
    for (int k = 0; k < NCHUNK; k++) {
        if (k < NCHUNK - 1) asm volatile("cp.async.wait_group 1;\n" ::: "memory");
        else                asm volatile("cp.async.wait_group 0;\n" ::: "memory");
        __syncthreads();

        if (k < NCHUNK - 2) {
            issue(srcPs, srcCs, smA + SM_PREV + bS * PREV_BUF, smA + SM_CURR + bS * CURR_BUF);
            srcPs += (size_t)CHUNK * PLANE * 4;
            srcCs += (size_t)CHUNK * PLANE * 4;
            bS = (bS == 2) ? 0 : bS + 1;
        }

        const char* pbuf = smem + SM_PREV + bC * PREV_BUF;
        const char* cbuf = smem + SM_CURR + bC * CURR_BUF;

        if (grp == 0) {
            #pragma unroll
            for (int cc = 0; cc < CHUNK; cc++) {
                PREAMBLE
                F2(aux[0], cv01, cv01); F2(aux[1], cv23, cv23);   // ssq
                F2(aux[2], cv45, cv45); F2(aux[3], cv67, cv67);
                FROW(0, rowB);                      // dy=-4: o0..4
                MROW(5, rowB + 528);                // dy=-1: o10..12
                const u64 p01 = LD1(rowB + 1056);   // o23 pair01 (dy+2 dx-4, floats s..s+1)
                F2(acc[32], cv01, p01);
            }
        } else if (grp == 1) {
            #pragma unroll
            for (int cc = 0; cc < CHUNK; cc++) {
                PREAMBLE
                if (doFB) { const ulonglong2 v = LD2(secB + fbOff); F2(aux[0], v.x, v.x); F2(aux[1], v.y, v.y); }
                FROW(0, rowB + 352);                // dy=-2: o5..9
                MROW(5, rowB + 880);                // dy=+1: o20..22
            }
        } else if (grp == 2) {
            #pragma unroll
            for (int cc = 0; cc < CHUNK; cc++) {
                PREAMBLE
                {   // dy=0: o13..19 + interior prev-sq (aux)
                    const char* rb = rowB + 704;
                    const ulonglong2 q0 = LD2(rb), q1 = LD2(rb + 16), q2 = LD2(rb + 32), q3 = LD2(rb + 48);
                    F2(aux[0], q1.x, q1.x); F2(aux[1], q1.y, q1.y);
                    F2(aux[2], q2.x, q2.x); F2(aux[3], q2.y, q2.y);
                    const u64 P34 = PK(HIW(q0.y), LOW(q1.x)), P56 = PK(HIW(q1.x), LOW(q1.y));
                    const u64 P78 = PK(HIW(q1.y), LOW(q2.x)), P9A = PK(HIW(q2.x), LOW(q2.y));
                    const u64 PBC = PK(HIW(q2.y), LOW(q3.x));
                    F2(acc[0],cv01,q0.x);  F2(acc[1],cv23,q0.y);  F2(acc[2],cv45,q1.x);  F2(acc[3],cv67,q1.y);
                    F2(acc[4],cv01,q0.y);  F2(acc[5],cv23,q1.x);  F2(acc[6],cv45,q1.y);  F2(acc[7],cv67,q2.x);
                    F2(acc[8],cv01,P34);   F2(acc[9],cv23,P56);   F2(acc[10],cv45,P78);  F2(acc[11],cv67,P9A);
                    F2(acc[12],cv01,q1.x); F2(acc[13],cv23,q1.y); F2(acc[14],cv45,q2.x); F2(acc[15],cv67,q2.y);
                    F2(acc[16],cv01,P56);  F2(acc[17],cv23,P78);  F2(acc[18],cv45,P9A);  F2(acc[19],cv67,PBC);
                    F2(acc[20],cv01,q1.y); F2(acc[21],cv23,q2.x); F2(acc[22],cv45,q2.y); F2(acc[23],cv67,q3.x);
                    F2(acc[24],cv01,q2.x); F2(acc[25],cv23,q2.y); F2(acc[26],cv45,q3.x); F2(acc[27],cv67,q3.y);
                }
                {   // dy=+2: o24 (dx-2) + o23 pair23
                    const char* rb6 = rowB + 1056;
                    const u64 d23 = LD1(rb6 + 8);          // floats s+2,s+3
                    const ulonglong2 m = LD2(rb6 + 16);    // floats s+4..s+7
                    const u64 d89 = LD1(rb6 + 32);         // floats s+8,s+9
                    F2(acc[28],cv01,d23); F2(acc[29],cv23,m.x); F2(acc[30],cv45,m.y); F2(acc[31],cv67,d89);
                    F2(acc[32], cv23, d23);                // o23 pixels 2,3
                }
            }
        } else {
            #pragma unroll
            for (int cc = 0; cc < CHUNK; cc++) {
                PREAMBLE
                if (doFB) { const ulonglong2 v = LD2(secB + fbOff); F2(aux[0], v.x, v.x); F2(aux[1], v.y, v.y); }
                FROW(0, rowB + 1408);               // dy=+4: o28..32
                {   // dy=+2 dx{0,2,4}: o25..o27 + o23 pairs45/67
                    const char* rb = rowB + 1056;
                    const ulonglong2 q1 = LD2(rb + 16), q2 = LD2(rb + 32), q3 = LD2(rb + 48);
                    F2(acc[20],cv01,q1.x); F2(acc[21],cv23,q1.y); F2(acc[22],cv45,q2.x); F2(acc[23],cv67,q2.y);  // o25
                    F2(acc[24],cv01,q1.y); F2(acc[25],cv23,q2.x); F2(acc[26],cv45,q2.y); F2(acc[27],cv67,q3.x);  // o26
                    F2(acc[28],cv01,q2.x); F2(acc[29],cv23,q2.y); F2(acc[30],cv45,q3.x); F2(acc[31],cv67,q3.y);  // o27
                    F2(acc[32], cv45, q1.x);               // o23 pixels 4,5
                    F2(acc[33], cv67, q1.y);               // o23 pixels 6,7
                }
            }
        }
        bC = (bC == 2) ? 0 : bC + 1;
    }

    // ---- epilogue: norms into smem ----
    {
        char* sspB = smem + SM_SSP;
        if (grp == 0) {   // curr inv-norms (aux = ssq)
            float4 c0, c1;
            c0.x = rsqrtf(FL(aux[0])); c0.y = rsqrtf(FH(aux[0]));
            c0.z = rsqrtf(FL(aux[1])); c0.w = rsqrtf(FH(aux[1]));
            c1.x = rsqrtf(FL(aux[2])); c1.y = rsqrtf(FH(aux[2]));
            c1.z = rsqrtf(FL(aux[3])); c1.w = rsqrtf(FH(aux[3]));
            char* cdst = smem + SM_CIV + ty * CROW + xg * 32;
            *(float4*)cdst = c0;
            *(float4*)(cdst + 16) = c1;
        } else if (grp == 2) {   // interior prev inv-norms (aux = sq)
            float4 w0, w1;
            w0.x = GRD(FL(aux[0])); w0.y = GRD(FH(aux[0]));
            w0.z = GRD(FL(aux[1])); w0.w = GRD(FH(aux[1]));
            w1.x = GRD(FL(aux[2])); w1.y = GRD(FH(aux[2]));
            w1.z = GRD(FL(aux[3])); w1.w = GRD(FH(aux[3]));
            char* dst = sspB + (ty + 4) * HROW + xg * 32 + 16;
            *(float4*)dst = w0;
            *(float4*)(dst + 16) = w1;
        }
        if (doFB) {       // boundary prev inv-norms (aux = fb)
            float4 w;
            w.x = GRD(FL(aux[0])); w.y = GRD(FH(aux[0]));
            w.z = GRD(FL(aux[1])); w.w = GRD(FH(aux[1]));
            *(float4*)(sspB + fbOff) = w;
        }
    }
    __syncthreads();

    u64 inv01, inv23, inv45, inv67;
    {
        const char* civ = smem + SM_CIV + ty * CROW + xg * 32;
        const ulonglong2 IA = LD2(civ), IB = LD2(civ + 16);
        inv01 = IA.x; inv23 = IA.y; inv45 = IB.x; inv67 = IB.y;
    }

    const char* srow = smem + SM_SSP + tyOff;
    char* outBase = (char*)(out + ((size_t)bb * 33 * HH + (y0 + ty)) * WW + x0 + xg * 8);

#define OST(PL, O, B0, B1, B2, B3) do { \
    ulonglong2 r0, r1; \
    r0.x = M2(M2(acc[(O)*4+0], inv01), (B0)); \
    r0.y = M2(M2(acc[(O)*4+1], inv23), (B1)); \
    r1.x = M2(M2(acc[(O)*4+2], inv45), (B2)); \
    r1.y = M2(M2(acc[(O)*4+3], inv67), (B3)); \
    char* _op = outBase + (size_t)(PL) * (PLANE * 4); \
    *(ulonglong2*)_op = r0; \
    *(ulonglong2*)(_op + 16) = r1; \
} while (0)

#define EFROW(SR, PL, O) do { \
    const ulonglong2 q0 = LD2(srow + (SR)), q1 = LD2(srow + (SR) + 16); \
    const ulonglong2 q2 = LD2(srow + (SR) + 32), q3 = LD2(srow + (SR) + 48); \
    OST((PL)+0, (O)+0, q0.x, q0.y, q1.x, q1.y); \
    OST((PL)+1, (O)+1, q0.y, q1.x, q1.y, q2.x); \
    OST((PL)+2, (O)+2, q1.x, q1.y, q2.x, q2.y); \
    OST((PL)+3, (O)+3, q1.y, q2.x, q2.y, q3.x); \
    OST((PL)+4, (O)+4, q2.x, q2.y, q3.x, q3.y); \
} while (0)

#define EMROW(SR, PL, O) do { \
    const unsigned f3 = *(const unsigned*)(srow + (SR) + 12); \
    const ulonglong2 q1 = LD2(srow + (SR) + 16), q2 = LD2(srow + (SR) + 32); \
    const unsigned f12 = *(const unsigned*)(srow + (SR) + 48); \
    const u64 P34 = PK(f3, LOW(q1.x)),        P56 = PK(HIW(q1.x), LOW(q1.y)); \
    const u64 P78 = PK(HIW(q1.y), LOW(q2.x)), P9A = PK(HIW(q2.x), LOW(q2.y)); \
    const u64 PBC = PK(HIW(q2.y), f12); \
    OST((PL)+0, (O)+0, P34, P56, P78, P9A); \
    OST((PL)+1, (O)+1, q1.x, q1.y, q2.x, q2.y); \
    OST((PL)+2, (O)+2, P56, P78, P9A, PBC); \
} while (0)

    char* o23base = outBase + (size_t)23 * (PLANE * 4);

    if (grp == 0) {
        EFROW(0, 0, 0);        // dy=-4: o0..4
        EMROW(528, 10, 5);     // dy=-1: o10..12
        {                      // o23 pixels 0,1
            const u64 n01 = LD1(srow + 1056);
            *(u64*)o23base = M2(M2(acc[32], inv01), n01);
        }
    } else if (grp == 1) {
        EFROW(352, 5, 0);      // dy=-2: o5..9
        EMROW(880, 20, 5);     // dy=+1: o20..22
    } else if (grp == 2) {
        {   // dy=0: o13..19
            const ulonglong2 q0 = LD2(srow + 704), q1 = LD2(srow + 720);
            const ulonglong2 q2 = LD2(srow + 736), q3 = LD2(srow + 752);
            const u64 P34 = PK(HIW(q0.y), LOW(q1.x)), P56 = PK(HIW(q1.x), LOW(q1.y));
            const u64 P78 = PK(HIW(q1.y), LOW(q2.x)), P9A = PK(HIW(q2.x), LOW(q2.y));
            const u64 PBC = PK(HIW(q2.y), LOW(q3.x));
            OST(13, 0, q0.x, q0.y, q1.x, q1.y);
            OST(14, 1, q0.y, q1.x, q1.y, q2.x);
            OST(15, 2, P34, P56, P78, P9A);
            OST(16, 3, q1.x, q1.y, q2.x, q2.y);
            OST(17, 4, P56, P78, P9A, PBC);
            OST(18, 5, q1.y, q2.x, q2.y, q3.x);
            OST(19, 6, q2.x, q2.y, q3.x, q3.y);
        }
        {   // o24 (dy+2, dx-2) + o23 pixels 2,3
            const u64 nd23 = LD1(srow + 1064);
            const ulonglong2 nm = LD2(srow + 1072);
            const u64 nd89 = LD1(srow + 1088);
            OST(24, 7, nd23, nm.x, nm.y, nd89);
            *(u64*)(o23base + 8) = M2(M2(acc[32], inv23), nd23);
        }
    } else {
        EFROW(1408, 28, 0);    // dy=+4: o28..32
        {   // dy=+2 dx{0,2,4}: o25..o27 + o23 pixels 4..7
            const ulonglong2 t1 = LD2(srow + 1072), t2 = LD2(srow + 1088), t3 = LD2(srow + 1104);
            OST(25, 5, t1.x, t1.y, t2.x, t2.y);
            OST(26, 6, t1.y, t2.x, t2.y, t3.x);
            OST(27, 7, t2.x, t2.y, t3.x, t3.y);
            *(u64*)(o23base + 16) = M2(M2(acc[32], inv45), t1.x);
            *(u64*)(o23base + 24) = M2(M2(acc[33], inv67), t1.y);
        }
    }
}

extern "C" void kernel_launch(void* const* d_in, const int* in_sizes, int n_in,
                              void* d_out, int out_size)
{
    const float* curr = (const float*)d_in[0];
    const float* prev = (const float*)d_in[1];
    float* out = (float*)d_out;

    cudaFuncSetAttribute(corr_kernel, cudaFuncAttributeMaxDynamicSharedMemorySize, SMEM_BYTES);

    dim3 grid(WW / TILE_W, HH / TILE_H, BB);   // 384 blocks
    corr_kernel<<<grid, NT, SMEM_BYTES>>>(curr, prev, out);
}

// round 13
// speedup vs baseline: 1.7977x; 1.0107x over previous
#include <cuda_runtime.h>
#include <cstdint>

#define HH 128
#define WW 192
#define CC_TOT 256
#define BB 8
#define TILE_W 32
#define TILE_H 16
#define HALO_H 24
#define CHUNK 8
#define NCHUNK (CC_TOT / CHUNK)          // 32
#define NT 256
#define PLANE ((size_t)HH * WW)

#define HROW 176
#define CROW 144
#define PSEC (HALO_H * HROW)              // 4224
#define CSEC (TILE_H * CROW)              // 2304
#define PREV_BUF (CHUNK * PSEC)           // 33792
#define CURR_BUF (CHUNK * CSEC)           // 18432
#define SM_PREV 0
#define SM_CURR (2 * PREV_BUF)            // 67584
#define SM_SSP  (SM_CURR + 2 * CURR_BUF)  // 104448
#define SM_CIV  (SM_SSP + PSEC)           // 108672
#define SMEM_BYTES (SM_CIV + CSEC)        // 110976 -> 2 CTAs/SM (113664 cap)

typedef unsigned long long u64;

__device__ __forceinline__ void F2(u64 &d, u64 a, u64 b) {
    asm("fma.rn.f32x2 %0, %1, %2, %0;" : "+l"(d) : "l"(a), "l"(b));
}
__device__ __forceinline__ u64 M2(u64 a, u64 b) {
    u64 d; asm("mul.rn.f32x2 %0, %1, %2;" : "=l"(d) : "l"(a), "l"(b)); return d;
}
__device__ __forceinline__ u64 PK(unsigned a, unsigned b) {
    u64 d; asm("mov.b64 %0, {%1, %2};" : "=l"(d) : "r"(a), "r"(b)); return d;
}
__device__ __forceinline__ unsigned LOW(u64 a) {
    unsigned l, h; asm("mov.b64 {%0, %1}, %2;" : "=r"(l), "=r"(h) : "l"(a)); return l;
}
__device__ __forceinline__ unsigned HIW(u64 a) {
    unsigned l, h; asm("mov.b64 {%0, %1}, %2;" : "=r"(l), "=r"(h) : "l"(a)); return h;
}
__device__ __forceinline__ float FL(u64 a) { return __uint_as_float(LOW(a)); }
__device__ __forceinline__ float FH(u64 a) { return __uint_as_float(HIW(a)); }
__device__ __forceinline__ void cp16(uint32_t dst, const void* src, int szbytes) {
    asm volatile("cp.async.cg.shared.global [%0], [%1], 16, %2;\n"
                 :: "r"(dst), "l"(src), "r"(szbytes) : "memory");
}
__device__ __forceinline__ ulonglong2 LD2(const void* p) {
    return *reinterpret_cast<const ulonglong2*>(p);
}
__device__ __forceinline__ u64 LD1(const void* p) {
    return *reinterpret_cast<const u64*>(p);
}
__device__ __forceinline__ float GRD(float v) { return v > 0.f ? rsqrtf(v) : 0.f; }

__global__ void __launch_bounds__(NT, 2)
corr_kernel(const float* __restrict__ curr, const float* __restrict__ prev,
            float* __restrict__ out)
{
    extern __shared__ char smem[];

    const int tid = threadIdx.x;
    const int grp = tid >> 6;          // 4 groups of 64 threads
    const int gt  = tid & 63;
    const int xg  = gt & 3;            // 4 x-groups of 8 pixels
    const int ty  = gt >> 2;           // 16 rows
    const int x0  = blockIdx.x * TILE_W;
    const int y0  = blockIdx.y * TILE_H;
    const int bb  = blockIdx.z;

    const char* currB = (const char*)(curr + (size_t)bb * CC_TOT * PLANE);
    const char* prevB = (const char*)(prev + (size_t)bb * CC_TOT * PLANE);
    const uint32_t smA = (uint32_t)__cvta_generic_to_shared(smem);

    // ---- staging precompute ----
    const int psy = tid / 10, psx = tid - psy * 10;   // 240 prev f4 slots (24 rows x 10)
    const int pgy = y0 - 4 + psy, pgx = x0 - 4 + psx * 4;
    const bool doP = (tid < 240);
    const bool pok = doP && ((unsigned)pgy < HH) && ((unsigned)pgx < WW);
    const int pOff = pok ? (pgy * WW + pgx) * 4 : 0;
    const int psz  = pok ? 16 : 0;
    const uint32_t pRel = (uint32_t)(psy * HROW + psx * 16);
    const bool doC = (tid >= 128);
    const int cslot = tid - 128;
    const int csy = cslot >> 3, csx = cslot & 7;
    const int cOff = ((y0 + csy) * WW + x0 + csx * 4) * 4;
    const uint32_t cRel = (uint32_t)(csy * CROW + csx * 16);

    // ---- boundary prev-sq: 112 slots on G1(56)/G3(56) ----
    int fbj = -1;
    if (grp == 1)      { if (gt < 56) fbj = gt; }
    else if (grp == 3) { if (gt < 56) fbj = 56 + gt; }
    const bool doFB = (fbj >= 0);
    int fbRow = 0, fbCol = 0;
    if (fbj >= 0) {
        if (fbj < 40)      { fbRow = fbj / 10; fbCol = fbj - fbRow * 10; }
        else if (fbj < 80) { int i = fbj - 40; fbRow = 20 + i / 10; fbCol = i - (i / 10) * 10; }
        else               { int i = fbj - 80; fbRow = 4 + (i >> 1); fbCol = (i & 1) ? 9 : 0; }
    }
    const uint32_t fbOff = (uint32_t)(fbRow * HROW + fbCol * 16);

    // ---- accumulators (same layout as R12) ----
    u64 acc[34];
    #pragma unroll
    for (int i = 0; i < 34; i++) acc[i] = 0ull;
    u64 aux[4];
    #pragma unroll
    for (int i = 0; i < 4; i++) aux[i] = 0ull;

    auto issue = [&](const char* srcP, const char* srcC, uint32_t dP, uint32_t dC) {
        #pragma unroll
        for (int cc = 0; cc < CHUNK; cc++) {
            const size_t so = (size_t)cc * PLANE * 4;
            if (doP) cp16(dP + cc * PSEC + pRel, srcP + so + pOff, psz);
            if (doC) cp16(dC + cc * CSEC + cRel, srcC + so + cOff, 16);
        }
        asm volatile("cp.async.commit_group;\n" ::: "memory");
    };

    // prologue: stage chunk 0 -> buf 0
    issue(prevB, currB, smA + SM_PREV, smA + SM_CURR);

    const char* srcPs = prevB + (size_t)CHUNK * PLANE * 4;   // chunk 1 source
    const char* srcCs = currB + (size_t)CHUNK * PLANE * 4;

    const int tyOff = ty * HROW + xg * 32;
    const int cvOff = ty * CROW + xg * 32;

#define FROW(O, RB) do { \
    const ulonglong2 q0 = LD2(RB), q1 = LD2((RB) + 16), q2 = LD2((RB) + 32), q3 = LD2((RB) + 48); \
    F2(acc[(O)*4+0],cv01,q0.x); F2(acc[(O)*4+1],cv23,q0.y); F2(acc[(O)*4+2],cv45,q1.x); F2(acc[(O)*4+3],cv67,q1.y); \
    F2(acc[(O)*4+4],cv01,q0.y); F2(acc[(O)*4+5],cv23,q1.x); F2(acc[(O)*4+6],cv45,q1.y); F2(acc[(O)*4+7],cv67,q2.x); \
    F2(acc[(O)*4+8],cv01,q1.x); F2(acc[(O)*4+9],cv23,q1.y); F2(acc[(O)*4+10],cv45,q2.x); F2(acc[(O)*4+11],cv67,q2.y); \
    F2(acc[(O)*4+12],cv01,q1.y); F2(acc[(O)*4+13],cv23,q2.x); F2(acc[(O)*4+14],cv45,q2.y); F2(acc[(O)*4+15],cv67,q3.x); \
    F2(acc[(O)*4+16],cv01,q2.x); F2(acc[(O)*4+17],cv23,q2.y); F2(acc[(O)*4+18],cv45,q3.x); F2(acc[(O)*4+19],cv67,q3.y); \
} while (0)

#define MROW(O, RB) do { \
    const unsigned f3 = *(const unsigned*)((RB) + 12); \
    const ulonglong2 q1 = LD2((RB) + 16), q2 = LD2((RB) + 32); \
    const unsigned f12 = *(const unsigned*)((RB) + 48); \
    const u64 P34 = PK(f3, LOW(q1.x)),      P56 = PK(HIW(q1.x), LOW(q1.y)); \
    const u64 P78 = PK(HIW(q1.y), LOW(q2.x)), P9A = PK(HIW(q2.x), LOW(q2.y)); \
    const u64 PBC = PK(HIW(q2.y), f12); \
    F2(acc[(O)*4+0],cv01,P34);  F2(acc[(O)*4+1],cv23,P56);  F2(acc[(O)*4+2],cv45,P78);  F2(acc[(O)*4+3],cv67,P9A); \
    F2(acc[(O)*4+4],cv01,q1.x); F2(acc[(O)*4+5],cv23,q1.y); F2(acc[(O)*4+6],cv45,q2.x); F2(acc[(O)*4+7],cv67,q2.y); \
    F2(acc[(O)*4+8],cv01,P56);  F2(acc[(O)*4+9],cv23,P78);  F2(acc[(O)*4+10],cv45,P9A); F2(acc[(O)*4+11],cv67,PBC); \
} while (0)

#define PREAMBLE \
    const char* secB = pbuf + cc * PSEC; \
    const char* rowB = secB + tyOff; \
    const char* cvP  = cbuf + cc * CSEC + cvOff; \
    const ulonglong2 CA = LD2(cvP), CB = LD2(cvP + 16); \
    const u64 cv01 = CA.x, cv23 = CA.y, cv45 = CB.x, cv67 = CB.y;

    #pragma unroll 1
    for (int k = 0; k < NCHUNK; k++) {
        asm volatile("cp.async.wait_group 0;\n" ::: "memory");
        __syncthreads();   // chunk k visible to all; all threads done computing chunk k-1

        if (k < NCHUNK - 1) {
            // stage chunk k+1 into the buffer vacated by chunk k-1
            issue(srcPs, srcCs,
                  smA + SM_PREV + ((k + 1) & 1) * PREV_BUF,
                  smA + SM_CURR + ((k + 1) & 1) * CURR_BUF);
            srcPs += (size_t)CHUNK * PLANE * 4;
            srcCs += (size_t)CHUNK * PLANE * 4;
        }

        const char* pbuf = smem + SM_PREV + (k & 1) * PREV_BUF;
        const char* cbuf = smem + SM_CURR + (k & 1) * CURR_BUF;

        if (grp == 0) {
            #pragma unroll 4
            for (int cc = 0; cc < CHUNK; cc++) {
                PREAMBLE
                F2(aux[0], cv01, cv01); F2(aux[1], cv23, cv23);   // ssq
                F2(aux[2], cv45, cv45); F2(aux[3], cv67, cv67);
                FROW(0, rowB);                      // dy=-4: o0..4
                MROW(5, rowB + 528);                // dy=-1: o10..12
                const u64 p01 = LD1(rowB + 1056);   // o23 pair01
                F2(acc[32], cv01, p01);
            }
        } else if (grp == 1) {
            #pragma unroll 4
            for (int cc = 0; cc < CHUNK; cc++) {
                PREAMBLE
                if (doFB) { const ulonglong2 v = LD2(secB + fbOff); F2(aux[0], v.x, v.x); F2(aux[1], v.y, v.y); }
                FROW(0, rowB + 352);                // dy=-2: o5..9
                MROW(5, rowB + 880);                // dy=+1: o20..22
            }
        } else if (grp == 2) {
            #pragma unroll 4
            for (int cc = 0; cc < CHUNK; cc++) {
                PREAMBLE
                {   // dy=0: o13..19 + interior prev-sq (aux)
                    const char* rb = rowB + 704;
                    const ulonglong2 q0 = LD2(rb), q1 = LD2(rb + 16), q2 = LD2(rb + 32), q3 = LD2(rb + 48);
                    F2(aux[0], q1.x, q1.x); F2(aux[1], q1.y, q1.y);
                    F2(aux[2], q2.x, q2.x); F2(aux[3], q2.y, q2.y);
                    const u64 P34 = PK(HIW(q0.y), LOW(q1.x)), P56 = PK(HIW(q1.x), LOW(q1.y));
                    const u64 P78 = PK(HIW(q1.y), LOW(q2.x)), P9A = PK(HIW(q2.x), LOW(q2.y));
                    const u64 PBC = PK(HIW(q2.y), LOW(q3.x));
                    F2(acc[0],cv01,q0.x);  F2(acc[1],cv23,q0.y);  F2(acc[2],cv45,q1.x);  F2(acc[3],cv67,q1.y);
                    F2(acc[4],cv01,q0.y);  F2(acc[5],cv23,q1.x);  F2(acc[6],cv45,q1.y);  F2(acc[7],cv67,q2.x);
                    F2(acc[8],cv01,P34);   F2(acc[9],cv23,P56);   F2(acc[10],cv45,P78);  F2(acc[11],cv67,P9A);
                    F2(acc[12],cv01,q1.x); F2(acc[13],cv23,q1.y); F2(acc[14],cv45,q2.x); F2(acc[15],cv67,q2.y);
                    F2(acc[16],cv01,P56);  F2(acc[17],cv23,P78);  F2(acc[18],cv45,P9A);  F2(acc[19],cv67,PBC);
                    F2(acc[20],cv01,q1.y); F2(acc[21],cv23,q2.x); F2(acc[22],cv45,q2.y); F2(acc[23],cv67,q3.x);
                    F2(acc[24],cv01,q2.x); F2(acc[25],cv23,q2.y); F2(acc[26],cv45,q3.x); F2(acc[27],cv67,q3.y);
                }
                {   // dy=+2: o24 (dx-2) + o23 pair23
                    const char* rb6 = rowB + 1056;
                    const u64 d23 = LD1(rb6 + 8);
                    const ulonglong2 m = LD2(rb6 + 16);
                    const u64 d89 = LD1(rb6 + 32);
                    F2(acc[28],cv01,d23); F2(acc[29],cv23,m.x); F2(acc[30],cv45,m.y); F2(acc[31],cv67,d89);
                    F2(acc[32], cv23, d23);
                }
            }
        } else {
            #pragma unroll 4
            for (int cc = 0; cc < CHUNK; cc++) {
                PREAMBLE
                if (doFB) { const ulonglong2 v = LD2(secB + fbOff); F2(aux[0], v.x, v.x); F2(aux[1], v.y, v.y); }
                FROW(0, rowB + 1408);               // dy=+4: o28..32
                {   // dy=+2 dx{0,2,4}: o25..o27 + o23 pairs45/67
                    const char* rb = rowB + 1056;
                    const ulonglong2 q1 = LD2(rb + 16), q2 = LD2(rb + 32), q3 = LD2(rb + 48);
                    F2(acc[20],cv01,q1.x); F2(acc[21],cv23,q1.y); F2(acc[22],cv45,q2.x); F2(acc[23],cv67,q2.y);
                    F2(acc[24],cv01,q1.y); F2(acc[25],cv23,q2.x); F2(acc[26],cv45,q2.y); F2(acc[27],cv67,q3.x);
                    F2(acc[28],cv01,q2.x); F2(acc[29],cv23,q2.y); F2(acc[30],cv45,q3.x); F2(acc[31],cv67,q3.y);
                    F2(acc[32], cv45, q1.x);
                    F2(acc[33], cv67, q1.y);
                }
            }
        }
    }

    // ---- epilogue: norms into smem ----
    {
        char* sspB = smem + SM_SSP;
        if (grp == 0) {
            float4 c0, c1;
            c0.x = rsqrtf(FL(aux[0])); c0.y = rsqrtf(FH(aux[0]));
            c0.z = rsqrtf(FL(aux[1])); c0.w = rsqrtf(FH(aux[1]));
            c1.x = rsqrtf(FL(aux[2])); c1.y = rsqrtf(FH(aux[2]));
            c1.z = rsqrtf(FL(aux[3])); c1.w = rsqrtf(FH(aux[3]));
            char* cdst = smem + SM_CIV + ty * CROW + xg * 32;
            *(float4*)cdst = c0;
            *(float4*)(cdst + 16) = c1;
        } else if (grp == 2) {
            float4 w0, w1;
            w0.x = GRD(FL(aux[0])); w0.y = GRD(FH(aux[0]));
            w0.z = GRD(FL(aux[1])); w0.w = GRD(FH(aux[1]));
            w1.x = GRD(FL(aux[2])); w1.y = GRD(FH(aux[2]));
            w1.z = GRD(FL(aux[3])); w1.w = GRD(FH(aux[3]));
            char* dst = sspB + (ty + 4) * HROW + xg * 32 + 16;
            *(float4*)dst = w0;
            *(float4*)(dst + 16) = w1;
        }
        if (doFB) {
            float4 w;
            w.x = GRD(FL(aux[0])); w.y = GRD(FH(aux[0]));
            w.z = GRD(FL(aux[1])); w.w = GRD(FH(aux[1]));
            *(float4*)(sspB + fbOff) = w;
        }
    }
    __syncthreads();

    u64 inv01, inv23, inv45, inv67;
    {
        const char* civ = smem + SM_CIV + ty * CROW + xg * 32;
        const ulonglong2 IA = LD2(civ), IB = LD2(civ + 16);
        inv01 = IA.x; inv23 = IA.y; inv45 = IB.x; inv67 = IB.y;
    }

    const char* srow = smem + SM_SSP + tyOff;
    char* outBase = (char*)(out + ((size_t)bb * 33 * HH + (y0 + ty)) * WW + x0 + xg * 8);

#define OST(PL, O, B0, B1, B2, B3) do { \
    ulonglong2 r0, r1; \
    r0.x = M2(M2(acc[(O)*4+0], inv01), (B0)); \
    r0.y = M2(M2(acc[(O)*4+1], inv23), (B1)); \
    r1.x = M2(M2(acc[(O)*4+2], inv45), (B2)); \
    r1.y = M2(M2(acc[(O)*4+3], inv67), (B3)); \
    char* _op = outBase + (size_t)(PL) * (PLANE * 4); \
    *(ulonglong2*)_op = r0; \
    *(ulonglong2*)(_op + 16) = r1; \
} while (0)

#define EFROW(SR, PL, O) do { \
    const ulonglong2 q0 = LD2(srow + (SR)), q1 = LD2(srow + (SR) + 16); \
    const ulonglong2 q2 = LD2(srow + (SR) + 32), q3 = LD2(srow + (SR) + 48); \
    OST((PL)+0, (O)+0, q0.x, q0.y, q1.x, q1.y); \
    OST((PL)+1, (O)+1, q0.y, q1.x, q1.y, q2.x); \
    OST((PL)+2, (O)+2, q1.x, q1.y, q2.x, q2.y); \
    OST((PL)+3, (O)+3, q1.y, q2.x, q2.y, q3.x); \
    OST((PL)+4, (O)+4, q2.x, q2.y, q3.x, q3.y); \
} while (0)

#define EMROW(SR, PL, O) do { \
    const unsigned f3 = *(const unsigned*)(srow + (SR) + 12); \
    const ulonglong2 q1 = LD2(srow + (SR) + 16), q2 = LD2(srow + (SR) + 32); \
    const unsigned f12 = *(const unsigned*)(srow + (SR) + 48); \
    const u64 P34 = PK(f3, LOW(q1.x)),        P56 = PK(HIW(q1.x), LOW(q1.y)); \
    const u64 P78 = PK(HIW(q1.y), LOW(q2.x)), P9A = PK(HIW(q2.x), LOW(q2.y)); \
    const u64 PBC = PK(HIW(q2.y), f12); \
    OST((PL)+0, (O)+0, P34, P56, P78, P9A); \
    OST((PL)+1, (O)+1, q1.x, q1.y, q2.x, q2.y); \
    OST((PL)+2, (O)+2, P56, P78, P9A, PBC); \
} while (0)

    char* o23base = outBase + (size_t)23 * (PLANE * 4);

    if (grp == 0) {
        EFROW(0, 0, 0);        // dy=-4: o0..4
        EMROW(528, 10, 5);     // dy=-1: o10..12
        {                      // o23 pixels 0,1
            const u64 n01 = LD1(srow + 1056);
            *(u64*)o23base = M2(M2(acc[32], inv01), n01);
        }
    } else if (grp == 1) {
        EFROW(352, 5, 0);      // dy=-2: o5..9
        EMROW(880, 20, 5);     // dy=+1: o20..22
    } else if (grp == 2) {
        {   // dy=0: o13..19
            const ulonglong2 q0 = LD2(srow + 704), q1 = LD2(srow + 720);
            const ulonglong2 q2 = LD2(srow + 736), q3 = LD2(srow + 752);
            const u64 P34 = PK(HIW(q0.y), LOW(q1.x)), P56 = PK(HIW(q1.x), LOW(q1.y));
            const u64 P78 = PK(HIW(q1.y), LOW(q2.x)), P9A = PK(HIW(q2.x), LOW(q2.y));
            const u64 PBC = PK(HIW(q2.y), LOW(q3.x));
            OST(13, 0, q0.x, q0.y, q1.x, q1.y);
            OST(14, 1, q0.y, q1.x, q1.y, q2.x);
            OST(15, 2, P34, P56, P78, P9A);
            OST(16, 3, q1.x, q1.y, q2.x, q2.y);
            OST(17, 4, P56, P78, P9A, PBC);
            OST(18, 5, q1.y, q2.x, q2.y, q3.x);
            OST(19, 6, q2.x, q2.y, q3.x, q3.y);
        }
        {   // o24 (dy+2, dx-2) + o23 pixels 2,3
            const u64 nd23 = LD1(srow + 1064);
            const ulonglong2 nm = LD2(srow + 1072);
            const u64 nd89 = LD1(srow + 1088);
            OST(24, 7, nd23, nm.x, nm.y, nd89);
            *(u64*)(o23base + 8) = M2(M2(acc[32], inv23), nd23);
        }
    } else {
        EFROW(1408, 28, 0);    // dy=+4: o28..32
        {   // dy=+2 dx{0,2,4}: o25..o27 + o23 pixels 4..7
            const ulonglong2 t1 = LD2(srow + 1072), t2 = LD2(srow + 1088), t3 = LD2(srow + 1104);
            OST(25, 5, t1.x, t1.y, t2.x, t2.y);
            OST(26, 6, t1.y, t2.x, t2.y, t3.x);
            OST(27, 7, t2.x, t2.y, t3.x, t3.y);
            *(u64*)(o23base + 16) = M2(M2(acc[32], inv45), t1.x);
            *(u64*)(o23base + 24) = M2(M2(acc[33], inv67), t1.y);
        }
    }
}

extern "C" void kernel_launch(void* const* d_in, const int* in_sizes, int n_in,
                              void* d_out, int out_size)
{
    const float* curr = (const float*)d_in[0];
    const float* prev = (const float*)d_in[1];
    float* out = (float*)d_out;

    cudaFuncSetAttribute(corr_kernel, cudaFuncAttributeMaxDynamicSharedMemorySize, SMEM_BYTES);

    dim3 grid(WW / TILE_W, HH / TILE_H, BB);   // 384 blocks
    corr_kernel<<<grid, NT, SMEM_BYTES>>>(curr, prev, out);
}